// round 17
// baseline (speedup 1.0000x reference)
#include <cuda_runtime.h>
#include <math.h>

// Problem constants (B,C,H,W,K) = (32,8,64,64,16)
#define BATCH 32
#define CHW    (8 * 64 * 64)           // 32768 elements per batch
#define N_ELEM (BATCH * CHW)           // 1,048,576
#define KMIX   16
#define TPB    256
#define EPB    (TPB / 2)               // 128 elements per block (2 threads/elem)
#define NBLK   (N_ELEM / EPB)          // 8192 blocks

__global__ void init_sldj_kernel(const float* __restrict__ sldj_in,
                                 float* __restrict__ sldj_out) {
    int i = threadIdx.x;
    if (i < BATCH) sldj_out[i] = sldj_in[i];
}

// 8 CTAs/SM at TPB=256 -> 2048 threads/SM (100% theoretical occupancy).
__global__ void __launch_bounds__(TPB, 8)
coupling_kernel(const float*  __restrict__ x_change,
                const float*  __restrict__ x_id,
                const float*  __restrict__ a,
                const float*  __restrict__ b,
                const float4* __restrict__ pi4,
                const float4* __restrict__ mu4,
                const float4* __restrict__ s4,
                float* __restrict__ out,       // [N_ELEM]
                float* __restrict__ out_id,    // [N_ELEM]
                float* __restrict__ sldj_out)  // [BATCH]
{
    const int tid  = threadIdx.x;
    const int half = tid & 1;                        // which 8 components
    const int e    = blockIdx.x * EPB + (tid >> 1);  // element index

    // ---- ALL loads front-batched: scalars + this thread's 6 float4 ----
    // Pair-duplicate scalar addresses are broadcast-dedup'd (same sectors).
    const float x   = __ldcs(&x_change[e]);
    const float av  = __ldcs(&a[e]);
    const float bv  = __ldcs(&b[e]);
    const float xid = __ldcs(&x_id[e]);

    const int base4 = e * (KMIX / 4) + half * 2;     // pair covers chunks 0..3

    // Linear-domain mixture accumulation over THIS thread's 8 components:
    //   e_k = exp(pi_k), es_k = exp(-s_k), z_k = (x-mu_k)*es_k
    //   t_k = exp(-z_k), sigma_k = 1/(1+t_k)
    //   S1 = sum e*sigma, S0 = sum e*t*sigma, P = sum e*es*t*sigma^2
    float S1 = 0.0f, S0 = 0.0f, P = 0.0f;
#pragma unroll
    for (int j = 0; j < 2; j++) {
        const float4 p4 = __ldcs(&pi4[base4 + j]);
        const float4 m4 = __ldcs(&mu4[base4 + j]);
        const float4 t4 = __ldcs(&s4[base4 + j]);

        const float pk[4] = {p4.x, p4.y, p4.z, p4.w};
        const float mk[4] = {m4.x, m4.y, m4.z, m4.w};
        const float sk[4] = {t4.x, t4.y, t4.z, t4.w};
#pragma unroll
        for (int q = 0; q < 4; q++) {
            const float ep = __expf(pk[q]);
            const float es = __expf(-sk[q]);
            const float z  = (x - mk[q]) * es;
            const float t  = __expf(-z);
            const float rc = __fdividef(1.0f, 1.0f + t);
            const float r1 = ep * rc;
            const float rt = r1 * t;
            S1 += r1;
            S0 += rt;
            P  += rt * (es * rc);
        }
    }

    // x_id passthrough: fire-and-forget, frees the register early.
    if (half == 0) __stcs(&out_id[e], xid);

    // Combine partner halves (lanes 2k <-> 2k+1); sums are order-invariant.
    S1 += __shfl_xor_sync(0xFFFFFFFFu, S1, 1);
    S0 += __shfl_xor_sync(0xFFFFFFFFu, S0, 1);
    P  += __shfl_xor_sync(0xFFFFFFFFu, P,  1);

    // Epilogue on the even lane of each pair only (fused logs: 2 instead of 4).
    //   out = (log(S1/S0) + b) * exp(a)
    //   ldj = log(P*(S1+S0)/(S1*S0)) + a
    float ldj = 0.0f;
    if (half == 0) {
        const float inv0  = __fdividef(1.0f, S0);
        const float ratio = S1 * inv0;
        const float larg  = __fdividef(P * (S1 + S0) * inv0, S1);
        __stcs(&out[e], (__logf(ratio) + bv) * __expf(av));
        ldj = __logf(larg) + av;
    }

    // ---- per-block reduction of ldj, then one atomic per block ----
    float v = ldj;                         // odd lanes contribute 0
#pragma unroll
    for (int off = 16; off > 0; off >>= 1)
        v += __shfl_down_sync(0xFFFFFFFFu, v, off);

    __shared__ float warp_sums[TPB / 32];
    const int lane = tid & 31;
    const int wid  = tid >> 5;
    if (lane == 0) warp_sums[wid] = v;
    __syncthreads();
    if (wid == 0) {
        float w = (lane < TPB / 32) ? warp_sums[lane] : 0.0f;
#pragma unroll
        for (int off = 4; off > 0; off >>= 1)
            w += __shfl_down_sync(0xFFu, w, off);
        if (lane == 0) {
            const int batch = blockIdx.x / (CHW / EPB);  // 256 blocks per batch
            atomicAdd(&sldj_out[batch], w);
        }
    }
}

extern "C" void kernel_launch(void* const* d_in, const int* in_sizes, int n_in,
                              void* d_out, int out_size) {
    // Inputs (metadata order): x_change, x_id, sldj, a, b, pi, mu, s
    const float* x_change = (const float*)d_in[0];
    const float* x_id     = (const float*)d_in[1];
    const float* sldj     = (const float*)d_in[2];
    const float* a        = (const float*)d_in[3];
    const float* b        = (const float*)d_in[4];
    const float4* pi4     = (const float4*)d_in[5];
    const float4* mu4     = (const float4*)d_in[6];
    const float4* s4      = (const float4*)d_in[7];

    float* out      = (float*)d_out;
    float* out_id   = out + N_ELEM;
    float* sldj_out = out + 2 * N_ELEM;

    init_sldj_kernel<<<1, 32>>>(sldj, sldj_out);
    coupling_kernel<<<NBLK, TPB>>>(x_change, x_id, a, b,
                                   pi4, mu4, s4,
                                   out, out_id, sldj_out);
}